// round 14
// baseline (speedup 1.0000x reference)
#include <cuda_runtime.h>
#include <cuda_bf16.h>

#define NUM_NODES 20000
#define NUM_EDGES 640000
#define NODE 128
#define ESZ 20
#define F3 384          // 3 * NODE

typedef unsigned long long u64;

// ---- packed f32x2 helpers (SASS FFMA2 — PTX-only) ----
__device__ __forceinline__ u64 pack2(float a, float b) {
    u64 r; asm("mov.b64 %0, {%1,%2};" : "=l"(r) : "f"(a), "f"(b)); return r;
}
__device__ __forceinline__ void unpack2(u64 v, float& a, float& b) {
    asm("mov.b64 {%0,%1}, %2;" : "=f"(a), "=f"(b) : "l"(v));
}
__device__ __forceinline__ u64 ffma2(u64 a, u64 b, u64 c) {
    u64 d; asm("fma.rn.f32x2 %0, %1, %2, %3;" : "=l"(d) : "l"(a), "l"(b), "l"(c));
    return d;
}

// scratch
__device__ float g_so[NUM_NODES * F3];   // scalar_output
__device__ int   g_cur[NUM_NODES];       // scan offsets / scatter cursors
__device__ int   g_eid[NUM_EDGES];       // edge ids sorted by dst

// ---------------------------------------------------------------------------
// Sort pipeline: counting sort of edge ids by dst
// ---------------------------------------------------------------------------
__global__ void zero_cnt_kernel() {
    int i = blockIdx.x * blockDim.x + threadIdx.x;
    if (i < NUM_NODES) g_cur[i] = 0;
}

__global__ void hist_kernel(const int* __restrict__ edges) {
    int e = blockIdx.x * blockDim.x + threadIdx.x;
    if (e < NUM_EDGES) atomicAdd(&g_cur[edges[2 * e + 1]], 1);
}

// single-block exclusive scan over g_cur (counts -> start offsets)
__global__ __launch_bounds__(1024) void scan_kernel() {
    __shared__ int warp_sums[32];
    __shared__ int s_carry;
    const int tid = threadIdx.x;
    const int lane = tid & 31, wid = tid >> 5;
    if (tid == 0) s_carry = 0;
    __syncthreads();
    for (int base = 0; base < NUM_NODES; base += 1024) {
        const int idx = base + tid;
        const int v = (idx < NUM_NODES) ? g_cur[idx] : 0;
        int incl = v;
        #pragma unroll
        for (int d = 1; d < 32; d <<= 1) {
            int t = __shfl_up_sync(~0u, incl, d);
            if (lane >= d) incl += t;
        }
        if (lane == 31) warp_sums[wid] = incl;
        __syncthreads();
        if (wid == 0) {
            int ws = warp_sums[lane];
            int wincl = ws;
            #pragma unroll
            for (int d = 1; d < 32; d <<= 1) {
                int t = __shfl_up_sync(~0u, wincl, d);
                if (lane >= d) wincl += t;
            }
            warp_sums[lane] = wincl - ws;   // exclusive warp offset
        }
        __syncthreads();
        const int excl = incl - v + warp_sums[wid] + s_carry;
        if (idx < NUM_NODES) g_cur[idx] = excl;
        __syncthreads();
        if (tid == 1023) s_carry = excl + v;
        __syncthreads();
    }
}

__global__ void scatter_kernel(const int* __restrict__ edges) {
    int e = blockIdx.x * blockDim.x + threadIdx.x;
    if (e < NUM_EDGES) {
        const int dst = edges[2 * e + 1];
        const int p = atomicAdd(&g_cur[dst], 1);
        g_eid[p] = e;
    }
}

// ---------------------------------------------------------------------------
// Node MLP -> g_so  (f32x2-packed)
// ---------------------------------------------------------------------------
#define NB 8
__global__ __launch_bounds__(128) void node_mlp_kernel(
    const float* __restrict__ ns, const float* __restrict__ W1,
    const float* __restrict__ b1, const float* __restrict__ W2,
    const float* __restrict__ b2) {
    __shared__ float xs[NB][NODE];
    __shared__ float hs[NB][NODE];
    const int tid = threadIdx.x;
    const int base = blockIdx.x * NB;

    #pragma unroll
    for (int n = 0; n < NB; n++)
        xs[n][tid] = ns[(base + n) * NODE + tid];
    __syncthreads();

    {
        u64 acc[NB];
        const float bb = b1[tid];
        #pragma unroll
        for (int n = 0; n < NB; n++) acc[n] = pack2(bb, 0.0f);
        #pragma unroll 4
        for (int kp = 0; kp < NODE / 2; kp++) {
            const u64 w = pack2(W1[(2 * kp) * NODE + tid],
                                W1[(2 * kp + 1) * NODE + tid]);
            #pragma unroll
            for (int n = 0; n < NB; n++) {
                const u64 x = *(const u64*)&xs[n][2 * kp];
                acc[n] = ffma2(x, w, acc[n]);
            }
        }
        #pragma unroll
        for (int n = 0; n < NB; n++) {
            float lo, hi; unpack2(acc[n], lo, hi);
            const float a = lo + hi;
            hs[n][tid] = a / (1.0f + __expf(-a));   // silu
        }
    }
    __syncthreads();

    #pragma unroll
    for (int jj = 0; jj < 3; jj++) {
        const int j = tid + jj * NODE;
        u64 acc[NB];
        const float bb = b2[j];
        #pragma unroll
        for (int n = 0; n < NB; n++) acc[n] = pack2(bb, 0.0f);
        #pragma unroll 4
        for (int kp = 0; kp < NODE / 2; kp++) {
            const u64 w = pack2(W2[(2 * kp) * F3 + j],
                                W2[(2 * kp + 1) * F3 + j]);
            #pragma unroll
            for (int n = 0; n < NB; n++) {
                const u64 h2 = *(const u64*)&hs[n][2 * kp];
                acc[n] = ffma2(h2, w, acc[n]);
            }
        }
        #pragma unroll
        for (int n = 0; n < NB; n++) {
            float lo, hi; unpack2(acc[n], lo, hi);
            g_so[(base + n) * F3 + j] = lo + hi;
        }
    }
}

// ---------------------------------------------------------------------------
// helpers
// ---------------------------------------------------------------------------
__device__ __forceinline__ void red4(float* p, float4 v) {
    asm volatile("red.global.add.v4.f32 [%0], {%1,%2,%3,%4};"
                 :: "l"(p), "f"(v.x), "f"(v.y), "f"(v.z), "f"(v.w)
                 : "memory");
}
__device__ __forceinline__ float4 fma4(float a, float4 b, float4 c) {
    return make_float4(fmaf(a, b.x, c.x), fmaf(a, b.y, c.y),
                       fmaf(a, b.z, c.z), fmaf(a, b.w, c.w));
}
__device__ __forceinline__ float4 mul4(float4 a, float4 b) {
    return make_float4(a.x * b.x, a.y * b.y, a.z * b.z, a.w * b.w);
}
__device__ __forceinline__ float4 add4(float4 a, float4 b) {
    return make_float4(a.x + b.x, a.y + b.y, a.z + b.z, a.w + b.w);
}
__device__ __forceinline__ float4 scale4(float4 a, float s) {
    return make_float4(a.x * s, a.y * s, a.z * s, a.w * s);
}

// ---------------------------------------------------------------------------
// Edge kernel over dst-sorted edge ids: filter GEMM (f32x2) + gating +
// run-merged reduction scatter. Each warp owns 16 CONSECUTIVE sorted edges
// (4 rounds x 4-edge register tile); messages for equal-dst runs merge in
// registers, one red4 group per run.
// ---------------------------------------------------------------------------
#define TE 128                 // edges per block
#define WE 4                   // edges per warp per round
#define ROUNDS 4               // 16 edges per warp

__global__ __launch_bounds__(256) void edge_kernel(
    const float* __restrict__ nss, const float* __restrict__ nsv,
    const float* __restrict__ est, const float* __restrict__ evec,
    const float* __restrict__ edist, const int* __restrict__ edges,
    const float* __restrict__ Wf, const float* __restrict__ bf,
    float* __restrict__ out) {
    __shared__ float4 sWf[ESZ * 96];   // 30720 B
    __shared__ float4 sBf[96];         // 1536 B
    __shared__ float  sEs[TE * ESZ];   // 10240 B (edge_state, sorted order)
    __shared__ int    sEid[TE];        // 512 B

    const int tid = threadIdx.x;
    const int warp = tid >> 5;
    const int lane = tid & 31;
    const int eblock = blockIdx.x * TE;

    // stage Wf, bf, eids, and (indirected) edge_state
    {
        const float4* wf4 = (const float4*)Wf;
        #pragma unroll
        for (int i = tid; i < ESZ * 96; i += 256) sWf[i] = wf4[i];
        if (tid < 96) sBf[tid] = ((const float4*)bf)[tid];
        if (tid < TE) sEid[tid] = g_eid[eblock + tid];
    }
    __syncthreads();
    {
        for (int i = tid; i < TE * ESZ; i += 256) {
            const int el = i / ESZ, k = i - el * ESZ;
            sEs[i] = __ldg(&est[(long)sEid[el] * ESZ + k]);
        }
    }
    __syncthreads();

    const ulonglong2* sWf2 = (const ulonglong2*)sWf;
    const ulonglong2* sBf2 = (const ulonglong2*)sBf;

    const int c = lane * 4;
    float* outv = out + (long)NUM_NODES * NODE;

    // run accumulators (carried across rounds)
    int cur_dst = -1;
    float4 accS, accV0, accV1, accV2;

    for (int r = 0; r < ROUNDS; r++) {
        const int elocal = warp * 16 + r * WE;   // contiguous 16 per warp

        // GEMM register tile: WE edges x 3 chunks x 2 f32x2
        u64 a0[WE][2], a1[WE][2], a2[WE][2];
        {
            const ulonglong2 b0 = sBf2[lane];
            const ulonglong2 b1v = sBf2[32 + lane];
            const ulonglong2 b2v = sBf2[64 + lane];
            #pragma unroll
            for (int i = 0; i < WE; i++) {
                a0[i][0] = b0.x;  a0[i][1] = b0.y;
                a1[i][0] = b1v.x; a1[i][1] = b1v.y;
                a2[i][0] = b2v.x; a2[i][1] = b2v.y;
            }
        }
        #pragma unroll
        for (int k = 0; k < ESZ; k++) {
            const ulonglong2 w0 = sWf2[k * 96 + lane];
            const ulonglong2 w1 = sWf2[k * 96 + 32 + lane];
            const ulonglong2 w2 = sWf2[k * 96 + 64 + lane];
            #pragma unroll
            for (int i = 0; i < WE; i++) {
                const float ek = sEs[(elocal + i) * ESZ + k];
                const u64 ek2 = pack2(ek, ek);
                a0[i][0] = ffma2(ek2, w0.x, a0[i][0]);
                a0[i][1] = ffma2(ek2, w0.y, a0[i][1]);
                a1[i][0] = ffma2(ek2, w1.x, a1[i][0]);
                a1[i][1] = ffma2(ek2, w1.y, a1[i][1]);
                a2[i][0] = ffma2(ek2, w2.x, a2[i][0]);
                a2[i][1] = ffma2(ek2, w2.y, a2[i][1]);
            }
        }

        // epilogue: per edge, gate + message; merge runs of equal dst
        #pragma unroll
        for (int i = 0; i < WE; i++) {
            const long e = (long)sEid[elocal + i];
            const int src = __ldg(&edges[2 * e]);
            const int dst = __ldg(&edges[2 * e + 1]);

            const float d = __ldg(&edist[e]);
            const float cut = (d < 5.0f)
                ? 0.5f * (__cosf(d * (3.14159265358979f / 5.0f)) + 1.0f) : 0.0f;

            const float v0 = __ldg(&evec[e * 3 + 0]);
            const float v1 = __ldg(&evec[e * 3 + 1]);
            const float v2 = __ldg(&evec[e * 3 + 2]);
            const float nrm = sqrtf(v0 * v0 + v1 * v1 + v2 * v2);
            const float inv = 1.0f / fmaxf(nrm, 1e-12f);
            const float env0 = v0 * inv, env1 = v1 * inv, env2 = v2 * inv;

            float4 fw0, fw1, fw2;
            unpack2(a0[i][0], fw0.x, fw0.y); unpack2(a0[i][1], fw0.z, fw0.w);
            unpack2(a1[i][0], fw1.x, fw1.y); unpack2(a1[i][1], fw1.z, fw1.w);
            unpack2(a2[i][0], fw2.x, fw2.y); unpack2(a2[i][1], fw2.z, fw2.w);

            const float4* sop = (const float4*)&g_so[(long)src * F3];
            const float4 fo0 = mul4(fw0, scale4(sop[lane],      cut));
            const float4 fo1 = mul4(fw1, scale4(sop[32 + lane], cut));
            const float4 fo2 = mul4(fw2, scale4(sop[64 + lane], cut));

            const float4 nssv = ((const float4*)&nss[(long)src * NODE])[lane];
            const float4 mS = mul4(nssv, fo2);

            const float4* nvp = (const float4*)&nsv[(long)src * 3 * NODE];
            float4 m0 = fma4(env0, fo1, mul4(nvp[lane],      fo0));
            float4 m1 = fma4(env1, fo1, mul4(nvp[32 + lane], fo0));
            float4 m2 = fma4(env2, fo1, mul4(nvp[64 + lane], fo0));

            if (dst == cur_dst) {
                accS = add4(accS, mS);
                accV0 = add4(accV0, m0);
                accV1 = add4(accV1, m1);
                accV2 = add4(accV2, m2);
            } else {
                if (cur_dst >= 0) {
                    red4(&out[(long)cur_dst * NODE + c], accS);
                    red4(&outv[(long)cur_dst * 3 * NODE + 0 * NODE + c], accV0);
                    red4(&outv[(long)cur_dst * 3 * NODE + 1 * NODE + c], accV1);
                    red4(&outv[(long)cur_dst * 3 * NODE + 2 * NODE + c], accV2);
                }
                cur_dst = dst;
                accS = mS; accV0 = m0; accV1 = m1; accV2 = m2;
            }
        }
    }
    // final flush
    if (cur_dst >= 0) {
        red4(&out[(long)cur_dst * NODE + c], accS);
        red4(&outv[(long)cur_dst * 3 * NODE + 0 * NODE + c], accV0);
        red4(&outv[(long)cur_dst * 3 * NODE + 1 * NODE + c], accV1);
        red4(&outv[(long)cur_dst * 3 * NODE + 2 * NODE + c], accV2);
    }
}

// ---------------------------------------------------------------------------
extern "C" void kernel_launch(void* const* d_in, const int* in_sizes, int n_in,
                              void* d_out, int out_size) {
    const float* nss   = (const float*)d_in[0];   // [20000,128]
    const float* nsv   = (const float*)d_in[1];   // [20000,3,128]
    const float* est   = (const float*)d_in[2];   // [640000,20]
    const float* evec  = (const float*)d_in[3];   // [640000,3]
    const float* edist = (const float*)d_in[4];   // [640000,1]
    const int*   edges = (const int*)d_in[5];     // [640000,2]
    const float* Wf    = (const float*)d_in[6];   // [20,384]
    const float* bf    = (const float*)d_in[7];   // [384]
    const float* W1    = (const float*)d_in[8];   // [128,128]
    const float* b1    = (const float*)d_in[9];   // [128]
    const float* W2    = (const float*)d_in[10];  // [128,384]
    const float* b2    = (const float*)d_in[11];  // [384]
    float* out = (float*)d_out;

    // init out = input node states (D2D copies; also shifts ncu capture window
    // onto a real kernel)
    cudaMemcpyAsync(out, nss, (size_t)NUM_NODES * NODE * sizeof(float),
                    cudaMemcpyDeviceToDevice);
    cudaMemcpyAsync(out + (size_t)NUM_NODES * NODE, nsv,
                    (size_t)NUM_NODES * 3 * NODE * sizeof(float),
                    cudaMemcpyDeviceToDevice);

    // counting sort of edges by dst
    zero_cnt_kernel<<<(NUM_NODES + 255) / 256, 256>>>();
    hist_kernel<<<(NUM_EDGES + 255) / 256, 256>>>(edges);
    scan_kernel<<<1, 1024>>>();
    scatter_kernel<<<(NUM_EDGES + 255) / 256, 256>>>(edges);

    node_mlp_kernel<<<NUM_NODES / NB, 128>>>(nss, W1, b1, W2, b2);
    edge_kernel<<<NUM_EDGES / TE, 256>>>(
        nss, nsv, est, evec, edist, edges, Wf, bf, out);
}